// round 4
// baseline (speedup 1.0000x reference)
#include <cuda_runtime.h>
#include <math.h>

// Problem shape (fixed by dataset): X is (65536, 512) fp32 row-major.
// NOTE: resubmission of the round-3 kernel — the round-3 bench died with a
// container-level infra error (same error previously seen in round 1 on a
// kernel that subsequently passed unchanged), so no metric data exists yet
// for this variant.
#define CDIM 512
#define BDIM 65536
#define NB1  2048            // pass-1 blocks (32 rows each, 2 parities)
#define R1   (BDIM / NB1)    // 32 rows per block, 16 per parity
#define NPART (NB1 * 2)      // 4096 partial rows
#define NB3  2048            // pass-3 blocks (32 rows each)
#define R3   (BDIM / NB3)    // 32

// Static device scratch (no allocations allowed).
__device__ __align__(16) float g_sumP[NPART][CDIM];
__device__ __align__(16) float g_maxP[NPART][CDIM];
__device__ __align__(16) float g_minP[NPART][CDIM];
__device__ __align__(16) float g_mean[CDIM];
__device__ __align__(16) float g_u[CDIM];
__device__ __align__(16) float g_dev[CDIM];
__device__ __align__(16) float g_c1[CDIM];
__device__ __align__(16) float g_c2[CDIM];
__device__ __align__(16) float g_wc[CDIM];
__device__ float g_sn1;

__device__ __forceinline__ float4 ldcs4(const float4* p) {
    return __ldcs(p);
}

// ---------------------------------------------------------------------------
// Pass 1: per-column partial sum / max / min. Block b covers rows
// [b*R1, (b+1)*R1); 256 threads = 128 column-groups x 2 row parities.
// Each thread accumulates 16 rows of its float4 column group. Streaming
// loads (__ldcs): X has zero reuse here, keep it out of L2.
// Partial row index = blockIdx*2 + parity (no intra-block combine needed).
// ---------------------------------------------------------------------------
__global__ void k_pass1(const float* __restrict__ X) {
    const int tc = threadIdx.x & 127;   // column group 0..127
    const int tr = threadIdx.x >> 7;    // row parity 0..1
    const int b = blockIdx.x;
    const float4* Xp = reinterpret_cast<const float4*>(X);
    size_t base = ((size_t)b * R1 + tr) * (CDIM / 4) + tc;

    float4 s  = make_float4(0.f, 0.f, 0.f, 0.f);
    float4 mx = make_float4(-INFINITY, -INFINITY, -INFINITY, -INFINITY);
    float4 mn = make_float4( INFINITY,  INFINITY,  INFINITY,  INFINITY);

#pragma unroll 8
    for (int r = 0; r < R1; r += 2) {
        float4 v = ldcs4(Xp + base + (size_t)r * (CDIM / 4));
        s.x += v.x; s.y += v.y; s.z += v.z; s.w += v.w;
        mx.x = fmaxf(mx.x, v.x); mx.y = fmaxf(mx.y, v.y);
        mx.z = fmaxf(mx.z, v.z); mx.w = fmaxf(mx.w, v.w);
        mn.x = fminf(mn.x, v.x); mn.y = fminf(mn.y, v.y);
        mn.z = fminf(mn.z, v.z); mn.w = fminf(mn.w, v.w);
    }
    const int p = b * 2 + tr;
    __stcs(reinterpret_cast<float4*>(g_sumP[p]) + tc, s);
    __stcs(reinterpret_cast<float4*>(g_maxP[p]) + tc, mx);
    __stcs(reinterpret_cast<float4*>(g_minP[p]) + tc, mn);
}

// ---------------------------------------------------------------------------
// Stage 2a: reduce the NPART partials per column (deterministic fixed-order
// tree). Block jb handles 4 columns. Emits mean[j], u[j], dev[j] where
// dev[j] = max_i |x[i,j] - mean[j]| = max(max-mean, mean-min).
// ---------------------------------------------------------------------------
__global__ void k_stage2a() {
    const int t  = threadIdx.x;   // 0..127
    const int jb = blockIdx.x;    // 0..127 (4 cols each)

    float4 s  = make_float4(0.f, 0.f, 0.f, 0.f);
    float4 mx = make_float4(-INFINITY, -INFINITY, -INFINITY, -INFINITY);
    float4 mn = make_float4( INFINITY,  INFINITY,  INFINITY,  INFINITY);

    for (int r = t; r < NPART; r += 128) {
        float4 vs = __ldcs(reinterpret_cast<const float4*>(&g_sumP[r][jb * 4]));
        float4 va = __ldcs(reinterpret_cast<const float4*>(&g_maxP[r][jb * 4]));
        float4 vi = __ldcs(reinterpret_cast<const float4*>(&g_minP[r][jb * 4]));
        s.x += vs.x; s.y += vs.y; s.z += vs.z; s.w += vs.w;
        mx.x = fmaxf(mx.x, va.x); mx.y = fmaxf(mx.y, va.y);
        mx.z = fmaxf(mx.z, va.z); mx.w = fmaxf(mx.w, va.w);
        mn.x = fminf(mn.x, vi.x); mn.y = fminf(mn.y, vi.y);
        mn.z = fminf(mn.z, vi.z); mn.w = fminf(mn.w, vi.w);
    }

    __shared__ float4 shS[128], shA[128], shI[128];
    shS[t] = s; shA[t] = mx; shI[t] = mn;
    __syncthreads();
    for (int off = 64; off > 0; off >>= 1) {
        if (t < off) {
            float4 a = shS[t], b2 = shS[t + off];
            a.x += b2.x; a.y += b2.y; a.z += b2.z; a.w += b2.w;
            shS[t] = a;
            float4 c = shA[t], d = shA[t + off];
            c.x = fmaxf(c.x, d.x); c.y = fmaxf(c.y, d.y);
            c.z = fmaxf(c.z, d.z); c.w = fmaxf(c.w, d.w);
            shA[t] = c;
            float4 e = shI[t], f = shI[t + off];
            e.x = fminf(e.x, f.x); e.y = fminf(e.y, f.y);
            e.z = fminf(e.z, f.z); e.w = fminf(e.w, f.w);
            shI[t] = e;
        }
        __syncthreads();
    }

    if (t == 0) {
        const float cb = (float)(1.0 / sqrt(2.0 * log((double)BDIM)));
        const float* ps = reinterpret_cast<const float*>(&shS[0]);
        const float* pa = reinterpret_cast<const float*>(&shA[0]);
        const float* pi = reinterpret_cast<const float*>(&shI[0]);
        for (int c = 0; c < 4; c++) {
            float mean = ps[c] * (1.0f / (float)BDIM);  // /2^16, exact scaling
            float uv   = cb * (pa[c] - pi[c]);
            float dev  = fmaxf(pa[c] - mean, mean - pi[c]);
            g_mean[jb * 4 + c] = mean;
            g_u[jb * 4 + c]    = uv;
            g_dev[jb * 4 + c]  = dev;
        }
    }
}

// ---------------------------------------------------------------------------
// Stage 2b: global scalars (dmax/wmax/bmax -> SN1/SN2/SN3) and per-column
// fused constants c1, c2 and clamped signed ww (g_wc). One block, 512 thr.
// ---------------------------------------------------------------------------
__device__ __forceinline__ float pow2_floor_log2(float v) {
    // replicates exp2(floor(log2(floor(v)))) including the v<1 -> 0 edge
    float f = floorf(v);
    if (f < 1.0f) return 0.0f;
    return ldexpf(1.0f, ilogbf(f));
}

__global__ void k_stage2b(const float* __restrict__ w,
                          const float* __restrict__ bia) {
    const int j = threadIdx.x;  // 0..511 (= column = w-group index)
    float dev = g_dev[j];
    float uv  = g_u[j];
    float wv  = w[j];
    float bv  = bia[j];

    __shared__ float sh[CDIM];
    __shared__ float s_dmax, s_wmax, s_sn1, s_sn2, s_sn3;

    // dmax = max over cols of max(|q|_col, |u|_col)
    sh[j] = fmaxf(dev, fabsf(uv));
    __syncthreads();
    for (int off = 256; off > 0; off >>= 1) {
        if (j < off) sh[j] = fmaxf(sh[j], sh[j + off]);
        __syncthreads();
    }
    if (j == 0) s_dmax = (sh[0] == 0.f) ? 1.f : sh[0];
    __syncthreads();

    sh[j] = fabsf(wv);
    __syncthreads();
    for (int off = 256; off > 0; off >>= 1) {
        if (j < off) sh[j] = fmaxf(sh[j], sh[j + off]);
        __syncthreads();
    }
    if (j == 0) s_wmax = (sh[0] == 0.f) ? 1.f : sh[0];
    __syncthreads();

    sh[j] = fabsf(bv);
    __syncthreads();
    for (int off = 256; off > 0; off >>= 1) {
        if (j < off) sh[j] = fmaxf(sh[j], sh[j + off]);
        __syncthreads();
    }
    if (j == 0) {
        float bmax = (sh[0] == 0.f) ? 1.f : sh[0];
        s_sn1 = pow2_floor_log2(32.0f / s_dmax);
        s_sn2 = pow2_floor_log2(32.0f / s_wmax);
        s_sn3 = pow2_floor_log2(32.0f / bmax);
        g_sn1 = s_sn1;
    }
    __syncthreads();

    const float SN1 = s_sn1, SN2 = s_sn2, SN3 = s_sn3;

    int uu = (int)(uv * SN1);       // trunc toward zero == astype(int32)
    int ww = (int)(wv * SN2);
    int bq = (int)(bv * SN3);

    int iu = min(abs(uu), 64);
    int ib = min(abs(bq), 64);
    float sgu = (uv > 0.f) ? 1.f : ((uv < 0.f) ? -1.f : 0.f);
    float sgb = (bv > 0.f) ? 1.f : ((bv < 0.f) ? -1.f : 0.f);
    float x8 = (float)(iu * ib) * sgu * sgb;

    float ssv = (float)uu * SN2 * SN3;
    g_c1[j] = SN3 / ssv;            // x7 coefficient
    g_c2[j] = x8 * SN2 / ssv;       // additive term

    int wc = max(-64, min(64, ww)); // signed-clamp == sign*clip(|.|,64)
    g_wc[j] = (float)wc;
}

// ---------------------------------------------------------------------------
// Pass 3: elementwise output. Block b covers rows [b*R3, b*R3+R3) — all in
// one w-group g = row>>7 (ww index from the repeat_interleave pairing:
// k//B == row>>7 exactly, since (row&127)*512+col <= 65535 < B).
// out = clamp((int)((x-mean)*SN1), +-64) * (wc[g]*c1[j]) + c2[j]
// 256 threads: 128 column-groups x 2 row parities. Streaming loads+stores
// (__ldcs/__stcs): zero reuse, bypass L2 retention.
// ---------------------------------------------------------------------------
__global__ void k_pass3(const float* __restrict__ X, float* __restrict__ O) {
    const int tc = threadIdx.x & 127;   // column group 0..127
    const int tr = threadIdx.x >> 7;    // row parity 0..1
    const int b = blockIdx.x;
    const int row0 = b * R3;
    const int g = row0 >> 7;            // 32-row blocks never straddle groups

    float4 m  = reinterpret_cast<const float4*>(g_mean)[tc];
    float4 c1 = reinterpret_cast<const float4*>(g_c1)[tc];
    float4 c2 = reinterpret_cast<const float4*>(g_c2)[tc];
    const float wg  = g_wc[g];
    const float sn1 = g_sn1;
    float4 e1;
    e1.x = wg * c1.x; e1.y = wg * c1.y; e1.z = wg * c1.z; e1.w = wg * c1.w;

    const float4* Xp = reinterpret_cast<const float4*>(X);
    float4* Op = reinterpret_cast<float4*>(O);
    size_t base = (size_t)(row0 + tr) * (CDIM / 4) + tc;

#pragma unroll 8
    for (int r = 0; r < R3; r += 2) {
        float4 v = ldcs4(Xp + base + (size_t)r * (CDIM / 4));
        float4 o;
        {
            int q = (int)((v.x - m.x) * sn1);
            q = max(-64, min(64, q));
            o.x = (float)q * e1.x + c2.x;
        }
        {
            int q = (int)((v.y - m.y) * sn1);
            q = max(-64, min(64, q));
            o.y = (float)q * e1.y + c2.y;
        }
        {
            int q = (int)((v.z - m.z) * sn1);
            q = max(-64, min(64, q));
            o.z = (float)q * e1.z + c2.z;
        }
        {
            int q = (int)((v.w - m.w) * sn1);
            q = max(-64, min(64, q));
            o.w = (float)q * e1.w + c2.w;
        }
        __stcs(Op + base + (size_t)r * (CDIM / 4), o);
    }
}

// ---------------------------------------------------------------------------
extern "C" void kernel_launch(void* const* d_in, const int* in_sizes, int n_in,
                              void* d_out, int out_size) {
    const float* X  = (const float*)d_in[0];   // (65536, 512)
    const float* w  = (const float*)d_in[1];   // (512,)
    const float* bi = (const float*)d_in[2];   // (512,)
    float* O = (float*)d_out;

    k_pass1<<<NB1, 256>>>(X);
    k_stage2a<<<CDIM / 4, 128>>>();
    k_stage2b<<<1, CDIM>>>(w, bi);
    k_pass3<<<NB3, 256>>>(X, O);
}

// round 5
// speedup vs baseline: 1.1808x; 1.1808x over previous
#include <cuda_runtime.h>
#include <math.h>

// X is (65536, 512) fp32 row-major.
#define CDIM 512
#define BDIM 65536
#define NB1  1024            // pass-1 blocks: 64 rows each, 2 parities -> 1 partial row
#define R1   (BDIM / NB1)    // 64
#define NB2  32              // stage-2a blocks: each reduces 32 partial rows
#define NB3  2048            // pass-3 blocks (32 rows each)
#define R3   (BDIM / NB3)    // 32

// Static device scratch (no allocations allowed).
__device__ __align__(16) float g_sumP[NB1][CDIM];
__device__ __align__(16) float g_maxP[NB1][CDIM];
__device__ __align__(16) float g_minP[NB1][CDIM];
__device__ __align__(16) float g_sum2[NB2][CDIM];
__device__ __align__(16) float g_max2[NB2][CDIM];
__device__ __align__(16) float g_min2[NB2][CDIM];
__device__ __align__(16) float g_mean[CDIM];
__device__ __align__(16) float g_c1[CDIM];
__device__ __align__(16) float g_c2[CDIM];
__device__ __align__(16) float g_wc[CDIM];
__device__ float g_sn1;

// ---------------------------------------------------------------------------
// Pass 1: per-column partial sum/max/min. Block b covers rows [b*64,(b+1)*64);
// 256 threads = 128 float4 column-groups x 2 row parities (32 rows each).
// DEFAULT cache policy on X loads — X (~128MiB) nearly fits L2 (~126MB) and
// pass3 re-reads it in reverse order to harvest the resident tail.
// Parities are combined through smem -> ONE partial row per block (keeps the
// partial footprint at 6 MiB and stage2a cheap). Partial writes use __stcs
// so they do not evict X from L2.
// ---------------------------------------------------------------------------
__global__ void k_pass1(const float* __restrict__ X) {
    const int tc = threadIdx.x & 127;   // column group 0..127
    const int tr = threadIdx.x >> 7;    // row parity 0..1
    const int b = blockIdx.x;
    const float4* Xp = reinterpret_cast<const float4*>(X);
    size_t base = ((size_t)b * R1 + tr) * (CDIM / 4) + tc;

    float4 s  = make_float4(0.f, 0.f, 0.f, 0.f);
    float4 mx = make_float4(-INFINITY, -INFINITY, -INFINITY, -INFINITY);
    float4 mn = make_float4( INFINITY,  INFINITY,  INFINITY,  INFINITY);

#pragma unroll 8
    for (int r = 0; r < R1; r += 2) {
        float4 v = Xp[base + (size_t)r * (CDIM / 4)];
        s.x += v.x; s.y += v.y; s.z += v.z; s.w += v.w;
        mx.x = fmaxf(mx.x, v.x); mx.y = fmaxf(mx.y, v.y);
        mx.z = fmaxf(mx.z, v.z); mx.w = fmaxf(mx.w, v.w);
        mn.x = fminf(mn.x, v.x); mn.y = fminf(mn.y, v.y);
        mn.z = fminf(mn.z, v.z); mn.w = fminf(mn.w, v.w);
    }

    __shared__ float4 shS[128], shA[128], shI[128];
    if (tr == 1) { shS[tc] = s; shA[tc] = mx; shI[tc] = mn; }
    __syncthreads();
    if (tr == 0) {
        float4 s2 = shS[tc], a2 = shA[tc], i2 = shI[tc];
        s.x += s2.x; s.y += s2.y; s.z += s2.z; s.w += s2.w;
        mx.x = fmaxf(mx.x, a2.x); mx.y = fmaxf(mx.y, a2.y);
        mx.z = fmaxf(mx.z, a2.z); mx.w = fmaxf(mx.w, a2.w);
        mn.x = fminf(mn.x, i2.x); mn.y = fminf(mn.y, i2.y);
        mn.z = fminf(mn.z, i2.z); mn.w = fminf(mn.w, i2.w);
        __stcs(reinterpret_cast<float4*>(g_sumP[b]) + tc, s);
        __stcs(reinterpret_cast<float4*>(g_maxP[b]) + tc, mx);
        __stcs(reinterpret_cast<float4*>(g_minP[b]) + tc, mn);
    }
}

// ---------------------------------------------------------------------------
// Stage 2a: 32 blocks x 512 threads. Block b reduces whole partial rows
// [b*32, b*32+32) across all 512 columns: thread j owns column j, so each
// row read is a fully-coalesced 2 KiB transaction (fixes the 8x overfetch
// of the strided-column scheme). Emits one row per block.
// ---------------------------------------------------------------------------
__global__ void k_stage2a() {
    const int j = threadIdx.x;    // column 0..511
    const int b = blockIdx.x;     // 0..31
    const int r0 = b * (NB1 / NB2);

    float s = 0.f, mx = -INFINITY, mn = INFINITY;
#pragma unroll 8
    for (int r = 0; r < NB1 / NB2; r++) {
        s += g_sumP[r0 + r][j];
        mx = fmaxf(mx, g_maxP[r0 + r][j]);
        mn = fminf(mn, g_minP[r0 + r][j]);
    }
    g_sum2[b][j] = s;
    g_max2[b][j] = mx;
    g_min2[b][j] = mn;
}

// ---------------------------------------------------------------------------
// Stage 2b: one block, 512 threads. Finishes the 32-row reduce per column,
// computes mean/u/dev, the three global maxima -> SN1/SN2/SN3, and the fused
// per-column constants used by pass3.
// ---------------------------------------------------------------------------
__device__ __forceinline__ float pow2_floor_log2(float v) {
    // replicates exp2(floor(log2(floor(v)))) including the v<1 -> 0 edge
    float f = floorf(v);
    if (f < 1.0f) return 0.0f;
    return ldexpf(1.0f, ilogbf(f));
}

__global__ void k_stage2b(const float* __restrict__ w,
                          const float* __restrict__ bia) {
    const int j = threadIdx.x;  // 0..511

    float s = 0.f, mx = -INFINITY, mn = INFINITY;
#pragma unroll
    for (int r = 0; r < NB2; r++) {
        s += g_sum2[r][j];
        mx = fmaxf(mx, g_max2[r][j]);
        mn = fminf(mn, g_min2[r][j]);
    }
    const float cb = (float)(1.0 / sqrt(2.0 * log((double)BDIM)));
    float mean = s * (1.0f / (float)BDIM);   // /2^16: exact scaling
    float uv   = cb * (mx - mn);
    float dev  = fmaxf(mx - mean, mean - mn);  // = max_i |x[i,j]-mean_j|

    float wv = w[j];
    float bv = bia[j];

    __shared__ float sh[CDIM];
    __shared__ float s_dmax, s_wmax, s_sn1, s_sn2, s_sn3;

    // dmax = max over cols of max(|q|_col, |u|_col)
    sh[j] = fmaxf(dev, fabsf(uv));
    __syncthreads();
    for (int off = 256; off > 0; off >>= 1) {
        if (j < off) sh[j] = fmaxf(sh[j], sh[j + off]);
        __syncthreads();
    }
    if (j == 0) s_dmax = (sh[0] == 0.f) ? 1.f : sh[0];
    __syncthreads();

    sh[j] = fabsf(wv);
    __syncthreads();
    for (int off = 256; off > 0; off >>= 1) {
        if (j < off) sh[j] = fmaxf(sh[j], sh[j + off]);
        __syncthreads();
    }
    if (j == 0) s_wmax = (sh[0] == 0.f) ? 1.f : sh[0];
    __syncthreads();

    sh[j] = fabsf(bv);
    __syncthreads();
    for (int off = 256; off > 0; off >>= 1) {
        if (j < off) sh[j] = fmaxf(sh[j], sh[j + off]);
        __syncthreads();
    }
    if (j == 0) {
        float bmax = (sh[0] == 0.f) ? 1.f : sh[0];
        s_sn1 = pow2_floor_log2(32.0f / s_dmax);
        s_sn2 = pow2_floor_log2(32.0f / s_wmax);
        s_sn3 = pow2_floor_log2(32.0f / bmax);
        g_sn1 = s_sn1;
    }
    __syncthreads();

    const float SN1 = s_sn1, SN2 = s_sn2, SN3 = s_sn3;

    int uu = (int)(uv * SN1);       // trunc toward zero == astype(int32)
    int ww = (int)(wv * SN2);
    int bq = (int)(bv * SN3);

    int iu = min(abs(uu), 64);
    int ib = min(abs(bq), 64);
    float sgu = (uv > 0.f) ? 1.f : ((uv < 0.f) ? -1.f : 0.f);
    float sgb = (bv > 0.f) ? 1.f : ((bv < 0.f) ? -1.f : 0.f);
    float x8 = (float)(iu * ib) * sgu * sgb;

    float ssv = (float)uu * SN2 * SN3;
    g_mean[j] = mean;
    g_c1[j]   = SN3 / ssv;          // x7 coefficient
    g_c2[j]   = x8 * SN2 / ssv;     // additive term

    int wc = max(-64, min(64, ww)); // signed-clamp == sign*clip(|.|,64)
    g_wc[j] = (float)wc;
}

// ---------------------------------------------------------------------------
// Pass 3: elementwise output, REVERSED block order. Block b covers rows
// [BDIM-(b+1)*32, BDIM-b*32): the first waves re-read the X region pass1
// touched most recently, which is still L2-resident (X ~= L2 capacity).
// X loads use default policy; OUTPUT stores use __stcs (evict-first) so the
// 128 MiB of written output does not evict X from L2 mid-pass.
// w-group g = row>>7 (repeat_interleave pairing: k//B == row>>7 exactly).
// out = clamp((int)((x-mean)*SN1), +-64) * (wc[g]*c1[j]) + c2[j]
// ---------------------------------------------------------------------------
__global__ void k_pass3(const float* __restrict__ X, float* __restrict__ O) {
    const int tc = threadIdx.x & 127;   // column group 0..127
    const int tr = threadIdx.x >> 7;    // row parity 0..1
    const int row0 = BDIM - (blockIdx.x + 1) * R3;   // reversed order
    const int g = row0 >> 7;            // 32-row blocks never straddle groups

    float4 m  = reinterpret_cast<const float4*>(g_mean)[tc];
    float4 c1 = reinterpret_cast<const float4*>(g_c1)[tc];
    float4 c2 = reinterpret_cast<const float4*>(g_c2)[tc];
    const float wg  = g_wc[g];
    const float sn1 = g_sn1;
    float4 e1;
    e1.x = wg * c1.x; e1.y = wg * c1.y; e1.z = wg * c1.z; e1.w = wg * c1.w;

    const float4* Xp = reinterpret_cast<const float4*>(X);
    float4* Op = reinterpret_cast<float4*>(O);
    size_t base = (size_t)(row0 + tr) * (CDIM / 4) + tc;

#pragma unroll 8
    for (int r = 0; r < R3; r += 2) {
        float4 v = Xp[base + (size_t)r * (CDIM / 4)];
        float4 o;
        {
            int q = (int)((v.x - m.x) * sn1);
            q = max(-64, min(64, q));
            o.x = (float)q * e1.x + c2.x;
        }
        {
            int q = (int)((v.y - m.y) * sn1);
            q = max(-64, min(64, q));
            o.y = (float)q * e1.y + c2.y;
        }
        {
            int q = (int)((v.z - m.z) * sn1);
            q = max(-64, min(64, q));
            o.z = (float)q * e1.z + c2.z;
        }
        {
            int q = (int)((v.w - m.w) * sn1);
            q = max(-64, min(64, q));
            o.w = (float)q * e1.w + c2.w;
        }
        __stcs(Op + base + (size_t)r * (CDIM / 4), o);
    }
}

// ---------------------------------------------------------------------------
extern "C" void kernel_launch(void* const* d_in, const int* in_sizes, int n_in,
                              void* d_out, int out_size) {
    const float* X  = (const float*)d_in[0];   // (65536, 512)
    const float* w  = (const float*)d_in[1];   // (512,)
    const float* bi = (const float*)d_in[2];   // (512,)
    float* O = (float*)d_out;

    k_pass1<<<NB1, 256>>>(X);
    k_stage2a<<<NB2, CDIM>>>();
    k_stage2b<<<1, CDIM>>>(w, bi);
    k_pass3<<<NB3, 256>>>(X, O);
}

// round 6
// speedup vs baseline: 1.2582x; 1.0656x over previous
#include <cuda_runtime.h>
#include <math.h>

// X is (65536, 512) fp32 row-major.
#define CDIM 512
#define BDIM 65536
#define NB1  2048            // pass-1 blocks: 32 rows each -> 1 partial row
#define R1   (BDIM / NB1)    // 32 rows per block, 16 per parity
#define NB2  64              // stage-2a blocks: each reduces 32 partial rows
#define NB3  2048            // pass-3 blocks (32 rows each)
#define R3   (BDIM / NB3)    // 32

// Static device scratch (no allocations allowed).
__device__ __align__(16) float g_sumP[NB1][CDIM];
__device__ __align__(16) float g_maxP[NB1][CDIM];
__device__ __align__(16) float g_minP[NB1][CDIM];
__device__ __align__(16) float g_sum2[NB2][CDIM];
__device__ __align__(16) float g_max2[NB2][CDIM];
__device__ __align__(16) float g_min2[NB2][CDIM];
__device__ __align__(16) float g_mean[CDIM];
__device__ __align__(16) float g_c1[CDIM];
__device__ __align__(16) float g_c2[CDIM];
__device__ __align__(16) float g_wc[CDIM];
__device__ float g_sn1;

// ---------------------------------------------------------------------------
// Pass 1: per-column partial sum/max/min. Block b covers rows [b*32,(b+1)*32);
// 256 threads = 128 float4 column-groups x 2 row parities (16 rows each).
// Loads are issued in explicit batches of 4 into temporaries BEFORE any
// accumulation, forcing MLP >= 4 per thread (the serial acc chain otherwise
// lets ptxas schedule load-use-load-use and halves streaming rate — this is
// the pass1-at-3.5TB/s-vs-pass3-at-6.4TB/s gap seen in R2/R5 profiles).
// Default cache policy on X (pass3 re-reads it; X ~ L2 capacity).
// Parities combine via smem -> ONE partial row per block (12 MiB total,
// __stcs so partials don't evict X).
// ---------------------------------------------------------------------------
__global__ void k_pass1(const float* __restrict__ X) {
    const int tc = threadIdx.x & 127;   // column group 0..127
    const int tr = threadIdx.x >> 7;    // row parity 0..1
    const int b = blockIdx.x;
    const float4* Xp = reinterpret_cast<const float4*>(X);
    // parity tr owns rows {tr, tr+2, ...} within the block's 32 rows
    size_t base = ((size_t)b * R1 + tr) * (CDIM / 4) + tc;
    const size_t rs = CDIM / 4;         // float4 row stride

    float4 s  = make_float4(0.f, 0.f, 0.f, 0.f);
    float4 mx = make_float4(-INFINITY, -INFINITY, -INFINITY, -INFINITY);
    float4 mn = make_float4( INFINITY,  INFINITY,  INFINITY,  INFINITY);

#pragma unroll
    for (int rr = 0; rr < R1 / 2; rr += 4) {        // 16 rows per parity
        // batch 4 independent loads first
        float4 v0 = Xp[base + (size_t)(2 * rr + 0) * rs];
        float4 v1 = Xp[base + (size_t)(2 * rr + 2) * rs];
        float4 v2 = Xp[base + (size_t)(2 * rr + 4) * rs];
        float4 v3 = Xp[base + (size_t)(2 * rr + 6) * rs];
        // then accumulate
        s.x += v0.x; s.y += v0.y; s.z += v0.z; s.w += v0.w;
        mx.x = fmaxf(mx.x, v0.x); mx.y = fmaxf(mx.y, v0.y);
        mx.z = fmaxf(mx.z, v0.z); mx.w = fmaxf(mx.w, v0.w);
        mn.x = fminf(mn.x, v0.x); mn.y = fminf(mn.y, v0.y);
        mn.z = fminf(mn.z, v0.z); mn.w = fminf(mn.w, v0.w);

        s.x += v1.x; s.y += v1.y; s.z += v1.z; s.w += v1.w;
        mx.x = fmaxf(mx.x, v1.x); mx.y = fmaxf(mx.y, v1.y);
        mx.z = fmaxf(mx.z, v1.z); mx.w = fmaxf(mx.w, v1.w);
        mn.x = fminf(mn.x, v1.x); mn.y = fminf(mn.y, v1.y);
        mn.z = fminf(mn.z, v1.z); mn.w = fminf(mn.w, v1.w);

        s.x += v2.x; s.y += v2.y; s.z += v2.z; s.w += v2.w;
        mx.x = fmaxf(mx.x, v2.x); mx.y = fmaxf(mx.y, v2.y);
        mx.z = fmaxf(mx.z, v2.z); mx.w = fmaxf(mx.w, v2.w);
        mn.x = fminf(mn.x, v2.x); mn.y = fminf(mn.y, v2.y);
        mn.z = fminf(mn.z, v2.z); mn.w = fminf(mn.w, v2.w);

        s.x += v3.x; s.y += v3.y; s.z += v3.z; s.w += v3.w;
        mx.x = fmaxf(mx.x, v3.x); mx.y = fmaxf(mx.y, v3.y);
        mx.z = fmaxf(mx.z, v3.z); mx.w = fmaxf(mx.w, v3.w);
        mn.x = fminf(mn.x, v3.x); mn.y = fminf(mn.y, v3.y);
        mn.z = fminf(mn.z, v3.z); mn.w = fminf(mn.w, v3.w);
    }

    __shared__ float4 shS[128], shA[128], shI[128];
    if (tr == 1) { shS[tc] = s; shA[tc] = mx; shI[tc] = mn; }
    __syncthreads();
    if (tr == 0) {
        float4 s2 = shS[tc], a2 = shA[tc], i2 = shI[tc];
        s.x += s2.x; s.y += s2.y; s.z += s2.z; s.w += s2.w;
        mx.x = fmaxf(mx.x, a2.x); mx.y = fmaxf(mx.y, a2.y);
        mx.z = fmaxf(mx.z, a2.z); mx.w = fmaxf(mx.w, a2.w);
        mn.x = fminf(mn.x, i2.x); mn.y = fminf(mn.y, i2.y);
        mn.z = fminf(mn.z, i2.z); mn.w = fminf(mn.w, i2.w);
        __stcs(reinterpret_cast<float4*>(g_sumP[b]) + tc, s);
        __stcs(reinterpret_cast<float4*>(g_maxP[b]) + tc, mx);
        __stcs(reinterpret_cast<float4*>(g_minP[b]) + tc, mn);
    }
}

// ---------------------------------------------------------------------------
// Stage 2a: 64 blocks x 512 threads. Block b reduces whole partial rows
// [b*32, b*32+32): thread j owns column j -> each row read is a fully
// coalesced 2 KiB transaction. Emits one row per block.
// ---------------------------------------------------------------------------
__global__ void k_stage2a() {
    const int j = threadIdx.x;    // column 0..511
    const int b = blockIdx.x;     // 0..63
    const int r0 = b * (NB1 / NB2);

    float s = 0.f, mx = -INFINITY, mn = INFINITY;
#pragma unroll 8
    for (int r = 0; r < NB1 / NB2; r++) {
        s += g_sumP[r0 + r][j];
        mx = fmaxf(mx, g_maxP[r0 + r][j]);
        mn = fminf(mn, g_minP[r0 + r][j]);
    }
    g_sum2[b][j] = s;
    g_max2[b][j] = mx;
    g_min2[b][j] = mn;
}

// ---------------------------------------------------------------------------
// Stage 2b: one block, 512 threads. Finishes the 64-row reduce per column,
// computes mean/u/dev, three global maxima -> SN1/SN2/SN3, and the fused
// per-column constants for pass3.
// ---------------------------------------------------------------------------
__device__ __forceinline__ float pow2_floor_log2(float v) {
    // replicates exp2(floor(log2(floor(v)))) including the v<1 -> 0 edge
    float f = floorf(v);
    if (f < 1.0f) return 0.0f;
    return ldexpf(1.0f, ilogbf(f));
}

__global__ void k_stage2b(const float* __restrict__ w,
                          const float* __restrict__ bia) {
    const int j = threadIdx.x;  // 0..511

    float s = 0.f, mx = -INFINITY, mn = INFINITY;
#pragma unroll
    for (int r = 0; r < NB2; r++) {
        s += g_sum2[r][j];
        mx = fmaxf(mx, g_max2[r][j]);
        mn = fminf(mn, g_min2[r][j]);
    }
    const float cb = (float)(1.0 / sqrt(2.0 * log((double)BDIM)));
    float mean = s * (1.0f / (float)BDIM);     // /2^16: exact scaling
    float uv   = cb * (mx - mn);
    float dev  = fmaxf(mx - mean, mean - mn);  // = max_i |x[i,j]-mean_j|

    float wv = w[j];
    float bv = bia[j];

    __shared__ float sh[CDIM];
    __shared__ float s_dmax, s_wmax, s_sn1, s_sn2, s_sn3;

    // dmax = max over cols of max(|q|_col, |u|_col)
    sh[j] = fmaxf(dev, fabsf(uv));
    __syncthreads();
    for (int off = 256; off > 0; off >>= 1) {
        if (j < off) sh[j] = fmaxf(sh[j], sh[j + off]);
        __syncthreads();
    }
    if (j == 0) s_dmax = (sh[0] == 0.f) ? 1.f : sh[0];
    __syncthreads();

    sh[j] = fabsf(wv);
    __syncthreads();
    for (int off = 256; off > 0; off >>= 1) {
        if (j < off) sh[j] = fmaxf(sh[j], sh[j + off]);
        __syncthreads();
    }
    if (j == 0) s_wmax = (sh[0] == 0.f) ? 1.f : sh[0];
    __syncthreads();

    sh[j] = fabsf(bv);
    __syncthreads();
    for (int off = 256; off > 0; off >>= 1) {
        if (j < off) sh[j] = fmaxf(sh[j], sh[j + off]);
        __syncthreads();
    }
    if (j == 0) {
        float bmax = (sh[0] == 0.f) ? 1.f : sh[0];
        s_sn1 = pow2_floor_log2(32.0f / s_dmax);
        s_sn2 = pow2_floor_log2(32.0f / s_wmax);
        s_sn3 = pow2_floor_log2(32.0f / bmax);
        g_sn1 = s_sn1;
    }
    __syncthreads();

    const float SN1 = s_sn1, SN2 = s_sn2, SN3 = s_sn3;

    int uu = (int)(uv * SN1);       // trunc toward zero == astype(int32)
    int ww = (int)(wv * SN2);
    int bq = (int)(bv * SN3);

    int iu = min(abs(uu), 64);
    int ib = min(abs(bq), 64);
    float sgu = (uv > 0.f) ? 1.f : ((uv < 0.f) ? -1.f : 0.f);
    float sgb = (bv > 0.f) ? 1.f : ((bv < 0.f) ? -1.f : 0.f);
    float x8 = (float)(iu * ib) * sgu * sgb;

    float ssv = (float)uu * SN2 * SN3;
    g_mean[j] = mean;
    g_c1[j]   = SN3 / ssv;          // x7 coefficient
    g_c2[j]   = x8 * SN2 / ssv;     // additive term

    int wc = max(-64, min(64, ww)); // signed-clamp == sign*clip(|.|,64)
    g_wc[j] = (float)wc;
}

// ---------------------------------------------------------------------------
// Pass 3: elementwise output, reversed block order (first waves hit the
// still-L2-resident tail of X). X loads default policy; output stores __stcs
// so the written stream doesn't evict X. w-group g = row>>7
// (repeat_interleave pairing: k//B == row>>7 exactly).
// out = clamp((int)((x-mean)*SN1), +-64) * (wc[g]*c1[j]) + c2[j]
// ---------------------------------------------------------------------------
__global__ void k_pass3(const float* __restrict__ X, float* __restrict__ O) {
    const int tc = threadIdx.x & 127;   // column group 0..127
    const int tr = threadIdx.x >> 7;    // row parity 0..1
    const int row0 = BDIM - (blockIdx.x + 1) * R3;   // reversed order
    const int g = row0 >> 7;            // 32-row blocks never straddle groups

    float4 m  = reinterpret_cast<const float4*>(g_mean)[tc];
    float4 c1 = reinterpret_cast<const float4*>(g_c1)[tc];
    float4 c2 = reinterpret_cast<const float4*>(g_c2)[tc];
    const float wg  = g_wc[g];
    const float sn1 = g_sn1;
    float4 e1;
    e1.x = wg * c1.x; e1.y = wg * c1.y; e1.z = wg * c1.z; e1.w = wg * c1.w;

    const float4* Xp = reinterpret_cast<const float4*>(X);
    float4* Op = reinterpret_cast<float4*>(O);
    size_t base = (size_t)(row0 + tr) * (CDIM / 4) + tc;

#pragma unroll 8
    for (int r = 0; r < R3; r += 2) {
        float4 v = Xp[base + (size_t)r * (CDIM / 4)];
        float4 o;
        {
            int q = (int)((v.x - m.x) * sn1);
            q = max(-64, min(64, q));
            o.x = (float)q * e1.x + c2.x;
        }
        {
            int q = (int)((v.y - m.y) * sn1);
            q = max(-64, min(64, q));
            o.y = (float)q * e1.y + c2.y;
        }
        {
            int q = (int)((v.z - m.z) * sn1);
            q = max(-64, min(64, q));
            o.z = (float)q * e1.z + c2.z;
        }
        {
            int q = (int)((v.w - m.w) * sn1);
            q = max(-64, min(64, q));
            o.w = (float)q * e1.w + c2.w;
        }
        __stcs(Op + base + (size_t)r * (CDIM / 4), o);
    }
}

// ---------------------------------------------------------------------------
extern "C" void kernel_launch(void* const* d_in, const int* in_sizes, int n_in,
                              void* d_out, int out_size) {
    const float* X  = (const float*)d_in[0];   // (65536, 512)
    const float* w  = (const float*)d_in[1];   // (512,)
    const float* bi = (const float*)d_in[2];   // (512,)
    float* O = (float*)d_out;

    k_pass1<<<NB1, 256>>>(X);
    k_stage2a<<<NB2, CDIM>>>();
    k_stage2b<<<1, CDIM>>>(w, bi);
    k_pass3<<<NB3, 256>>>(X, O);
}